// round 14
// baseline (speedup 1.0000x reference)
#include <cuda_runtime.h>
#include <cstdint>

// Problem constants
constexpr int B = 8;
constexpr int S = 4096;
constexpr int D = 2048;
constexpr int E = 64;

// Persistent-kernel layout
constexpr int THR    = 256;
constexpr int GRID   = 148 * 4;         // 592: co-resident at __launch_bounds__(256,4)

// Work-stealing chunks (exactly R2's measured-fastest streaming shape):
// chunk = (pair, sub): pair = (b, dtile) in [0,16), sub in [0,128), 32 rows x 1024 cols
constexpr int PAIRS      = B * 2;       // 16
constexpr int SUBS       = 128;
constexpr int NCHUNKS    = PAIRS * SUBS;  // 2048
constexpr int CHUNK_ROWS = S / SUBS;      // 32

constexpr int FOLD_BLOCKS   = 32;       // blocks [0,32): fold phase
constexpr int EXPERT_BLOCKS = E;        // blocks [32,96): one expert each

// Static scratch (allocation-free rule)
__device__ float g_partial[(size_t)NCHUNKS * 1024]; // 8 MB, one 1024-float partial per chunk
__device__ float g_mean[B * D];                     // 64 KB
__device__ float g_logits[B * E];                   // 2 KB
__device__ int   g_work;                            // chunk ticket (zero-init; reset at end)
__device__ int   g_c0;                              // phase-1 arrivals
__device__ int   g_c1;                              // fold arrivals
__device__ int   g_c2;                              // gemv ticket

// ---------------------------------------------------------------------------
// ONE persistent kernel, dynamic phase-1:
//  Phase 1 (all 592 blocks): steal 32-row x 1024-col chunks via g_work ticket
//    (next-chunk atomic prefetched during current chunk -> latency hidden).
//    Partial for chunk c -> g_partial[c] (content chunk-determined, so the
//    dynamic assignment stays deterministic).
//  Phase 2 (blocks 0..31): spin g_c0==592, fold 128 partials/position -> g_mean.
//  Phase 3 (blocks 32..95 = expert e): stage W[e] to smem after stealing ends
//    (overlaps other blocks' streaming), spin g_c1==32, warp b = dot(mean[b],W[e]).
//  Phase 4: ticket-last expert block: top-2 (strict > = lowest-index
//    tie-break, matches jax.lax.top_k) + 2-way softmax, counter reset.
// All cross-block sync: monotonic counters + threadfence release/acquire;
// all float reductions fixed-order -> bit-deterministic across replays.
// Output: out[0..15] = weights[B][2], out[16..31] = (float)indices[B][2].
// ---------------------------------------------------------------------------
__global__ __launch_bounds__(THR, 4) void fused_kernel(const float* __restrict__ x,
                                                       const float* __restrict__ W,
                                                       const float* __restrict__ bias,
                                                       float* __restrict__ out) {
    int bid = blockIdx.x;
    int tid = threadIdx.x;

    __shared__ int    s_chunk;
    __shared__ float4 wsm[D / 4];          // 8 KB (expert blocks)
    __shared__ float  s_logits[B * E];     // 2 KB (ticket block)
    __shared__ int    s_ticket;

    // ---------------- Phase 1: work-stealing partial sums ----------------
    if (tid == 0) s_chunk = atomicAdd(&g_work, 1);
    __syncthreads();
    int chunk = s_chunk;
    while (chunk < NCHUNKS) {
        __syncthreads();                                  // all threads have read s_chunk
        if (tid == 0) s_chunk = atomicAdd(&g_work, 1);    // prefetch next ticket

        int pair = chunk & (PAIRS - 1);
        int sub  = chunk >> 4;
        int b    = pair >> 1;
        int dt   = pair & 1;
        const float4* __restrict__ xp =
            (const float4*)(x + ((size_t)b * S + (size_t)sub * CHUNK_ROWS) * D
                              + dt * 1024 + tid * 4);
        float4 acc = make_float4(0.f, 0.f, 0.f, 0.f);
#pragma unroll 8
        for (int s = 0; s < CHUNK_ROWS; s++) {
            float4 v = __ldcs(xp + (size_t)s * (D / 4));
            acc.x += v.x; acc.y += v.y; acc.z += v.z; acc.w += v.w;
        }
        *(float4*)(g_partial + (size_t)chunk * 1024 + tid * 4) = acc;

        __syncthreads();                                  // next ticket visible
        chunk = s_chunk;
    }
    __syncthreads();
    if (tid == 0) {
        __threadfence();                    // release partial writes
        atomicAdd(&g_c0, 1);
    }

    if (bid >= FOLD_BLOCKS + EXPERT_BLOCKS) return;       // blocks 96..591 done

    if (bid < FOLD_BLOCKS) {
        // ---------------- Phase 2: fold -> g_mean ----------------
        if (tid == 0) {
            while (*(volatile int*)&g_c0 != GRID) __nanosleep(32);
            __threadfence();                // acquire all partials
        }
        __syncthreads();

        int idx = bid * THR + tid;          // float2 index over B*D: 0..8191
        int p   = idx >> 9;                 // pair owning this position
        int j2  = idx & 511;                // float2 within the 1024-float slice
        const float* base = g_partial + (size_t)p * 1024 + j2 * 2;
        float ax = 0.f, ay = 0.f;
#pragma unroll 16
        for (int s = 0; s < SUBS; s++) {    // chunk (pair p, sub s) = s*16 + p
            float2 v = *(const float2*)(base + (size_t)s * (PAIRS * 1024));
            ax += v.x; ay += v.y;
        }
        const float inv = 1.0f / (float)S;
        int bb = p >> 1, dd = p & 1;
        *(float2*)(g_mean + (size_t)bb * D + dd * 1024 + j2 * 2)
            = make_float2(ax * inv, ay * inv);

        __syncthreads();
        if (tid == 0) {
            __threadfence();                // release mean writes
            atomicAdd(&g_c1, 1);
        }
        return;
    }

    // ---------------- Phase 3: expert block (GEMV) ----------------
    int e    = bid - FOLD_BLOCKS;           // 0..63
    int lane = tid & 31;
    int bb   = tid >> 5;                    // warp = batch 0..7

    // Stage W[e] into smem — overlaps with remaining streaming / fold work
    {
        const float4* __restrict__ wp = (const float4*)(W + (size_t)e * D);
#pragma unroll
        for (int i = tid; i < D / 4; i += THR) wsm[i] = wp[i];
    }

    if (tid == 0) {
        while (*(volatile int*)&g_c1 != FOLD_BLOCKS) __nanosleep(32);
        __threadfence();                    // acquire g_mean
    }
    __syncthreads();

    {
        const float4* __restrict__ xp = (const float4*)(g_mean + (size_t)bb * D);
        float sum = 0.f;
#pragma unroll
        for (int i = 0; i < (D / 4) / 32; i++) {   // 16 float4 per lane
            int idx   = lane + i * 32;
            float4 w4 = wsm[idx];
            float4 x4 = xp[idx];
            sum += w4.x * x4.x + w4.y * x4.y + w4.z * x4.z + w4.w * x4.w;
        }
#pragma unroll
        for (int o = 16; o > 0; o >>= 1) sum += __shfl_xor_sync(0xffffffffu, sum, o);
        if (lane == 0) g_logits[bb * E + e] = sum + bias[e];
    }
    __syncthreads();

    // ---------------- Phase 4: ticket -> top-2 + softmax ----------------
    if (tid == 0) {
        __threadfence();                    // release this block's logits
        int t = atomicAdd(&g_c2, 1);
        if (t == EXPERT_BLOCKS - 1) __threadfence();   // acquire all logits
        s_ticket = t;
    }
    __syncthreads();

    if (s_ticket == EXPERT_BLOCKS - 1) {
        for (int i = tid; i < B * E; i += THR) s_logits[i] = g_logits[i];
        __syncthreads();

        if (tid < B) {
            const float* lg = s_logits + tid * E;
            float v1 = -1e30f, v2 = -1e30f;
            int   i1 = 0, i2 = 0;
#pragma unroll
            for (int k = 0; k < E; k++) {
                float v = lg[k];
                if (v > v1) { v2 = v1; i2 = i1; v1 = v; i1 = k; }
                else if (v > v2) { v2 = v; i2 = k; }
            }
            float e2 = __expf(v2 - v1);     // stable 2-way softmax
            float denom = 1.0f + e2;
            out[tid * 2 + 0]      = 1.0f / denom;
            out[tid * 2 + 1]      = e2 / denom;
            out[16 + tid * 2 + 0] = (float)i1;
            out[16 + tid * 2 + 1] = (float)i2;
        }
        __syncthreads();
        if (tid == 0) {                     // reset for next graph replay;
            __threadfence();                // all counter users have passed by now
            g_work = 0;
            g_c0 = 0;
            g_c1 = 0;
            g_c2 = 0;
        }
    }
}

extern "C" void kernel_launch(void* const* d_in, const int* in_sizes, int n_in,
                              void* d_out, int out_size) {
    const float* x    = (const float*)d_in[0];  // [B, S, D] fp32
    const float* W    = (const float*)d_in[1];  // [E, D]   fp32
    const float* bias = (const float*)d_in[2];  // [E]      fp32
    float* out        = (float*)d_out;          // 32 floats: weights then indices

    fused_kernel<<<GRID, THR>>>(x, W, bias, out);
}